// round 3
// baseline (speedup 1.0000x reference)
#include <cuda_runtime.h>
#include <cuda_bf16.h>
#include <cstdint>

// out[b,f] = -2.5*log10( sum_l A[b,l] * (trans[f,l]*w[l]) )
// Stage 1: wt_kernel -> g_wt bf16 [F,L] (2MB, L2-resident)
// Stage 2: split-K=2 bf16 mma.sync GEMM -> fp32 partials in g_part
// Stage 3: reduce_log_kernel: add halves, -2.5*log10
//
// NOTE: tcgen05 is NOT available: harness PTX targets compute_103 (no 'a'),
// ptxas rejects tcgen05.*. HMMA via mma.sync is the tensor path.

#define BMg 128
#define BNg 128
#define BKg 64
#define THREADS 512
#define A_ST_BYTES (BMg * BKg * 2)   // 16KB bf16
#define B_ST_BYTES (BNg * BKg * 2)   // 16KB bf16
#define DYN_SMEM ((A_ST_BYTES + B_ST_BYTES) * 2 + 1024)

// weighted filter matrix, bf16 (F=128, L=8192)
__device__ __align__(16) __nv_bfloat16 g_wt[128 * 8192];
// split-K partial sums: [2][B=8192][F=128] fp32 = 8MB
__device__ __align__(16) float g_part[2 * 8192 * 128];

__global__ void wt_kernel(const float* __restrict__ trans,
                          const float* __restrict__ lam, int F, int L) {
    int idx = blockIdx.x * blockDim.x + threadIdx.x;
    if (idx >= F * L) return;
    int l = idx % L;
    float w = 0.f;
    if (l < L - 1) w += 0.5f * (lam[l + 1] - lam[l]);
    if (l > 0)     w += 0.5f * (lam[l] - lam[l - 1]);
    g_wt[idx] = __float2bfloat16(trans[idx] * w);
}

__device__ __forceinline__ uint32_t smem_u32(const void* p) {
    uint32_t a;
    asm("{ .reg .u64 t; cvta.to.shared.u64 t, %1; cvt.u32.u64 %0, t; }"
        : "=r"(a) : "l"(p));
    return a;
}

__device__ __forceinline__ void ldmx4(uint32_t* r, uint32_t addr) {
    asm volatile("ldmatrix.sync.aligned.m8n8.x4.shared.b16 {%0,%1,%2,%3}, [%4];\n"
                 : "=r"(r[0]), "=r"(r[1]), "=r"(r[2]), "=r"(r[3]) : "r"(addr));
}

__device__ __forceinline__ void mma16816(float* c, const uint32_t* a, const uint32_t* b) {
    asm volatile("mma.sync.aligned.m16n8k16.row.col.f32.bf16.bf16.f32 "
                 "{%0,%1,%2,%3}, {%4,%5,%6,%7}, {%8,%9}, {%0,%1,%2,%3};\n"
                 : "+f"(c[0]), "+f"(c[1]), "+f"(c[2]), "+f"(c[3])
                 : "r"(a[0]), "r"(a[1]), "r"(a[2]), "r"(a[3]), "r"(b[0]), "r"(b[1]));
}

__device__ __forceinline__ uint32_t packbf2(float x, float y) {
    __nv_bfloat162 h = __floats2bfloat162_rn(x, y);
    return reinterpret_cast<uint32_t&>(h);
}

__device__ __forceinline__ void cp_async16(uint32_t dst, const void* src) {
    asm volatile("cp.async.ca.shared.global [%0], [%1], 16;"
                 :: "r"(dst), "l"(src) : "memory");
}
#define CP_COMMIT() asm volatile("cp.async.commit_group;" ::: "memory")
#define CP_WAIT0()  asm volatile("cp.async.wait_group 0;" ::: "memory")

__global__ void __launch_bounds__(THREADS, 1)
gemm_partial_kernel(const float* __restrict__ A, int K) {
    extern __shared__ char dynsmem[];
    const uint32_t base = (smem_u32(dynsmem) + 1023) & ~1023u;

    const int tid  = threadIdx.x;
    const int lane = tid & 31;
    const int warp = tid >> 5;
    const int wmBase = (warp & 3) * 32;    // 4 warps along M
    const int wnBase = (warp >> 2) * 32;   // 4 warps along N
    const size_t bm0 = (size_t)blockIdx.x * BMg;
    const int   kz  = blockIdx.y;          // split-K index
    const int   k0  = kz * (K >> 1);
    const int   NKT = (K >> 1) / BKg;      // 64

    // A staging: thread t -> row r = t>>2, float4 chunks 4c..4c+3 (c = t&3)
    const int ar = tid >> 2;
    const int ac = tid & 3;
    const int K4 = K >> 2;
    const float4* aRow = reinterpret_cast<const float4*>(A) + (bm0 + ar) * K4
                       + (k0 >> 2) + 4 * ac;
    const uint32_t aSmemRow = base + (uint32_t)ar * 128;  // per-stage offset added later
    const uint32_t aSw0 = (uint32_t)((2 * ac)     ^ (ar & 7)) * 16;
    const uint32_t aSw1 = (uint32_t)((2 * ac + 1) ^ (ar & 7)) * 16;

    // B staging via cp.async: chunk ids tid and tid+512
    const int bn0 = tid >> 3,        bc0 = tid & 7;
    const int bn1 = (tid + 512) >> 3, bc1 = (tid + 512) & 7;
    const __nv_bfloat16* bSrc0 = g_wt + (size_t)bn0 * K + k0 + bc0 * 8;
    const __nv_bfloat16* bSrc1 = g_wt + (size_t)bn1 * K + k0 + bc1 * 8;
    const uint32_t bDst0 = (uint32_t)bn0 * 128 + (uint32_t)((bc0 ^ (bn0 & 7)) * 16);
    const uint32_t bDst1 = (uint32_t)bn1 * 128 + (uint32_t)((bc1 ^ (bn1 & 7)) * 16);
    const uint32_t bBase = base + 2 * A_ST_BYTES;

    float acc[2][4][4];
#pragma unroll
    for (int i = 0; i < 2; i++)
#pragma unroll
        for (int j = 0; j < 4; j++)
#pragma unroll
            for (int k = 0; k < 4; k++) acc[i][j][k] = 0.f;

    int arow[2], brow[2];
#pragma unroll
    for (int mi = 0; mi < 2; mi++) arow[mi] = wmBase + mi * 16 + (lane & 15);
#pragma unroll
    for (int nj = 0; nj < 2; nj++) brow[nj] = wnBase + nj * 16 + ((lane >> 4) << 3) + (lane & 7);
    const int achalf = lane >> 4;
    const int bchalf = (lane >> 3) & 1;

    float4 fa[4];

    // ---- prologue: tile 0 into stage 0 ----
    {
        cp_async16(bBase + bDst0, bSrc0);
        cp_async16(bBase + bDst1, bSrc1);
        CP_COMMIT();
#pragma unroll
        for (int j = 0; j < 4; j++) fa[j] = aRow[j];
        uint4 c0 = { packbf2(fa[0].x, fa[0].y), packbf2(fa[0].z, fa[0].w),
                     packbf2(fa[1].x, fa[1].y), packbf2(fa[1].z, fa[1].w) };
        uint4 c1 = { packbf2(fa[2].x, fa[2].y), packbf2(fa[2].z, fa[2].w),
                     packbf2(fa[3].x, fa[3].y), packbf2(fa[3].z, fa[3].w) };
        *reinterpret_cast<uint4*>((char*)nullptr + 0); // no-op placeholder removed below
    }
    // (placeholder removed — real stores:)
    {
        asm volatile("st.shared.v4.b32 [%0], {%1,%2,%3,%4};" ::
            "r"(aSmemRow + aSw0),
            "r"(packbf2(fa[0].x, fa[0].y)), "r"(packbf2(fa[0].z, fa[0].w)),
            "r"(packbf2(fa[1].x, fa[1].y)), "r"(packbf2(fa[1].z, fa[1].w)) : "memory");
        asm volatile("st.shared.v4.b32 [%0], {%1,%2,%3,%4};" ::
            "r"(aSmemRow + aSw1),
            "r"(packbf2(fa[2].x, fa[2].y)), "r"(packbf2(fa[2].z, fa[2].w)),
            "r"(packbf2(fa[3].x, fa[3].y)), "r"(packbf2(fa[3].z, fa[3].w)) : "memory");
        CP_WAIT0();
    }
    __syncthreads();

    for (int kt = 0; kt < NKT; kt++) {
        const int st = kt & 1, nst = st ^ 1;
        const bool more = (kt + 1 < NKT);
        if (more) {
            const uint32_t bOff = bBase + (uint32_t)nst * B_ST_BYTES;
            cp_async16(bOff + bDst0, bSrc0 + (size_t)(kt + 1) * BKg);
            cp_async16(bOff + bDst1, bSrc1 + (size_t)(kt + 1) * BKg);
            CP_COMMIT();
            const float4* ap = aRow + (size_t)(kt + 1) * (BKg >> 2);
#pragma unroll
            for (int j = 0; j < 4; j++) fa[j] = ap[j];
        }
        // ---- compute current tile ----
        const uint32_t aoff = base + (uint32_t)st * A_ST_BYTES;
        const uint32_t boff = bBase + (uint32_t)st * B_ST_BYTES;
#pragma unroll
        for (int ks = 0; ks < 4; ks++) {
            uint32_t a[2][4], b[2][4];
#pragma unroll
            for (int mi = 0; mi < 2; mi++) {
                int c = ks * 2 + achalf;
                ldmx4(a[mi], aoff + (uint32_t)(arow[mi] * 8 + (c ^ (arow[mi] & 7))) * 16);
            }
#pragma unroll
            for (int nj = 0; nj < 2; nj++) {
                int c = ks * 2 + bchalf;
                ldmx4(b[nj], boff + (uint32_t)(brow[nj] * 8 + (c ^ (brow[nj] & 7))) * 16);
            }
#pragma unroll
            for (int mi = 0; mi < 2; mi++)
#pragma unroll
                for (int nt = 0; nt < 4; nt++)
                    mma16816(acc[mi][nt], a[mi], &b[nt >> 1][(nt & 1) * 2]);
        }
        if (more) {
            const uint32_t aDst = aSmemRow + (uint32_t)nst * A_ST_BYTES;
            asm volatile("st.shared.v4.b32 [%0], {%1,%2,%3,%4};" ::
                "r"(aDst + aSw0),
                "r"(packbf2(fa[0].x, fa[0].y)), "r"(packbf2(fa[0].z, fa[0].w)),
                "r"(packbf2(fa[1].x, fa[1].y)), "r"(packbf2(fa[1].z, fa[1].w)) : "memory");
            asm volatile("st.shared.v4.b32 [%0], {%1,%2,%3,%4};" ::
                "r"(aDst + aSw1),
                "r"(packbf2(fa[2].x, fa[2].y)), "r"(packbf2(fa[2].z, fa[2].w)),
                "r"(packbf2(fa[3].x, fa[3].y)), "r"(packbf2(fa[3].z, fa[3].w)) : "memory");
            CP_WAIT0();
        }
        __syncthreads();
    }

    // ---- store fp32 partials ----
    float* part = g_part + (size_t)kz * (8192 * 128);
#pragma unroll
    for (int mi = 0; mi < 2; mi++) {
        const size_t row0 = bm0 + wmBase + mi * 16 + (lane >> 2);
#pragma unroll
        for (int nt = 0; nt < 4; nt++) {
            const int col = wnBase + nt * 8 + (lane & 3) * 2;
            float2 v0 = { acc[mi][nt][0], acc[mi][nt][1] };
            float2 v1 = { acc[mi][nt][2], acc[mi][nt][3] };
            *reinterpret_cast<float2*>(part + row0 * BNg + col)       = v0;
            *reinterpret_cast<float2*>(part + (row0 + 8) * BNg + col) = v1;
        }
    }
}

__global__ void reduce_log_kernel(float* __restrict__ out, int n4) {
    int i = blockIdx.x * blockDim.x + threadIdx.x;
    if (i >= n4) return;
    const float4* p0 = reinterpret_cast<const float4*>(g_part);
    const float4* p1 = reinterpret_cast<const float4*>(g_part + 8192 * 128);
    float4 a = p0[i], b = p1[i];
    float4 r;
    r.x = -2.5f * log10f(a.x + b.x);
    r.y = -2.5f * log10f(a.y + b.y);
    r.z = -2.5f * log10f(a.z + b.z);
    r.w = -2.5f * log10f(a.w + b.w);
    reinterpret_cast<float4*>(out)[i] = r;
}

extern "C" void kernel_launch(void* const* d_in, const int* in_sizes, int n_in,
                              void* d_out, int out_size) {
    const float* l_target = (const float*)d_in[0];   // [B, L] fp32
    const float* trans    = (const float*)d_in[1];   // [F, L] fp32
    const float* lam      = (const float*)d_in[2];   // [L]    fp32

    const int L = in_sizes[2];
    const int F = in_sizes[1] / L;   // 128
    const int B = in_sizes[0] / L;   // 8192
    float* out = (float*)d_out;

    cudaFuncSetAttribute(gemm_partial_kernel,
                         cudaFuncAttributeMaxDynamicSharedMemorySize, DYN_SMEM);

    wt_kernel<<<(F * L + 255) / 256, 256>>>(trans, lam, F, L);
    dim3 grid(B / BMg, 2);
    gemm_partial_kernel<<<grid, THREADS, DYN_SMEM>>>(l_target, L);
    int n4 = (B * F) / 4;
    reduce_log_kernel<<<(n4 + 255) / 256, 256>>>(out, n4);
}

// round 5
// speedup vs baseline: 1.3576x; 1.3576x over previous
#include <cuda_runtime.h>
#include <cuda_bf16.h>
#include <cstdint>

// out[b,f] = -2.5*log10( sum_l A[b,l] * (trans[f,l]*w[l]) )
// wt_kernel -> g_wt bf16 [F,L] (2MB, L2-resident)
// gemm_log_kernel: bf16 mma.sync, 4-stage cp.async for A(fp32) and B(bf16),
//                  self-owned fp32->bf16 conversion, 1 barrier/tile, log10 epilogue.
// (tcgen05 unavailable: harness ptxas targets compute_103 which rejects it.)

#define BM 64
#define BN 128
#define BK 64
#define THREADS 256
#define B_ST   16384   // BN*BK*2
#define A32_ST 16384   // BM*BK*4
#define ABF_ST 8192    // BM*BK*2
// layout: B[4] | Abf[2] | A32[4]
#define OFF_ABF (4 * B_ST)
#define OFF_A32 (OFF_ABF + 2 * ABF_ST)
#define DYN_SMEM (OFF_A32 + 4 * A32_ST + 1024)

__device__ __align__(16) __nv_bfloat16 g_wt[128 * 8192];

__global__ void wt_kernel(const float* __restrict__ trans,
                          const float* __restrict__ lam, int F, int L) {
    int i4 = blockIdx.x * blockDim.x + threadIdx.x;
    int total = (F * L) >> 2;
    if (i4 >= total) return;
    int l0 = (i4 % (L >> 2)) << 2;
    float4 t = reinterpret_cast<const float4*>(trans)[i4];
    float w[4];
#pragma unroll
    for (int j = 0; j < 4; j++) {
        int l = l0 + j;
        int hi = l + 1 < L ? l + 1 : L - 1;
        int lo = l > 0 ? l - 1 : 0;
        w[j] = 0.5f * (__ldg(lam + hi) - __ldg(lam + lo));
    }
    __nv_bfloat162 p0 = __floats2bfloat162_rn(t.x * w[0], t.y * w[1]);
    __nv_bfloat162 p1 = __floats2bfloat162_rn(t.z * w[2], t.w * w[3]);
    uint2 v = { reinterpret_cast<uint32_t&>(p0), reinterpret_cast<uint32_t&>(p1) };
    reinterpret_cast<uint2*>(g_wt)[i4] = v;
}

__device__ __forceinline__ uint32_t smem_u32(const void* p) {
    uint32_t a;
    asm("{ .reg .u64 t; cvta.to.shared.u64 t, %1; cvt.u32.u64 %0, t; }"
        : "=r"(a) : "l"(p));
    return a;
}
__device__ __forceinline__ void ldmx4(uint32_t* r, uint32_t addr) {
    asm volatile("ldmatrix.sync.aligned.m8n8.x4.shared.b16 {%0,%1,%2,%3}, [%4];\n"
                 : "=r"(r[0]), "=r"(r[1]), "=r"(r[2]), "=r"(r[3]) : "r"(addr));
}
__device__ __forceinline__ void mma16816(float* c, const uint32_t* a, const uint32_t* b) {
    asm volatile("mma.sync.aligned.m16n8k16.row.col.f32.bf16.bf16.f32 "
                 "{%0,%1,%2,%3}, {%4,%5,%6,%7}, {%8,%9}, {%0,%1,%2,%3};\n"
                 : "+f"(c[0]), "+f"(c[1]), "+f"(c[2]), "+f"(c[3])
                 : "r"(a[0]), "r"(a[1]), "r"(a[2]), "r"(a[3]), "r"(b[0]), "r"(b[1]));
}
__device__ __forceinline__ uint32_t packbf2(float x, float y) {
    __nv_bfloat162 h = __floats2bfloat162_rn(x, y);
    return reinterpret_cast<uint32_t&>(h);
}
__device__ __forceinline__ void cp16(uint32_t dst, const void* src) {
    asm volatile("cp.async.cg.shared.global [%0], [%1], 16;"
                 :: "r"(dst), "l"(src) : "memory");
}
#define CP_COMMIT() asm volatile("cp.async.commit_group;" ::: "memory")
#define CP_WAIT2()  asm volatile("cp.async.wait_group 2;" ::: "memory")

__global__ void __launch_bounds__(THREADS, 1)
gemm_log_kernel(const float* __restrict__ A, float* __restrict__ out, int K) {
    extern __shared__ char dynsmem[];
    const uint32_t base = (smem_u32(dynsmem) + 1023) & ~1023u;
    const uint32_t bB   = base;
    const uint32_t bAbf = base + OFF_ABF;
    const uint32_t bA32 = base + OFF_A32;

    const int tid  = threadIdx.x;
    const int lane = tid & 31;
    const int warp = tid >> 5;
    const size_t bm0 = (size_t)blockIdx.x * BM;
    const int NKT = K / BK;

    // ---- A cp mapping: thread -> row ar, 64B (16 floats) starting col 16*ac
    const int ar = tid >> 2, ac = tid & 3;
    const float* aSrc = A + (bm0 + ar) * (size_t)K + ac * 16;
    const uint32_t a32rel = (uint32_t)ar * 256 + (uint32_t)((ac ^ (ar & 3)) * 64);
    // bf16 store chunks for this thread's 16 cols
    const uint32_t abfrel0 = (uint32_t)ar * 128 + (uint32_t)(((2 * ac)     ^ (ar & 7)) * 16);
    const uint32_t abfrel1 = (uint32_t)ar * 128 + (uint32_t)(((2 * ac + 1) ^ (ar & 7)) * 16);

    // ---- B cp mapping: 4 chunks per thread
    int brel[4];
    const __nv_bfloat16* bsrc[4];
#pragma unroll
    for (int j = 0; j < 4; j++) {
        int id = tid + 256 * j;
        int n = id >> 3, cc = id & 7;
        brel[j] = n * 128 + ((cc ^ (n & 7)) * 16);
        bsrc[j] = g_wt + (size_t)n * K + cc * 8;
    }

    // ---- mma fragment indexing (warp tile 32x32; 2 warps M x 4 warps N)
    const int wmBase = (warp & 1) * 32;
    const int wnBase = (warp >> 1) * 32;
    int arow[2], brow[2];
#pragma unroll
    for (int mi = 0; mi < 2; mi++) arow[mi] = wmBase + mi * 16 + (lane & 15);
#pragma unroll
    for (int nj = 0; nj < 2; nj++) brow[nj] = wnBase + nj * 16 + ((lane >> 4) << 3) + (lane & 7);
    const int achalf = lane >> 4;
    const int bchalf = (lane >> 3) & 1;

    float acc[2][4][4];
#pragma unroll
    for (int i = 0; i < 2; i++)
#pragma unroll
        for (int j = 0; j < 4; j++)
#pragma unroll
            for (int k = 0; k < 4; k++) acc[i][j][k] = 0.f;

#define ISSUE_TILE(T) do {                                                    \
        const int _s = (T) & 3;                                               \
        const float* _as = aSrc + (size_t)(T) * BK;                           \
        const uint32_t _ad = bA32 + (uint32_t)_s * A32_ST + a32rel;           \
        cp16(_ad,      _as);                                                  \
        cp16(_ad + 16, _as + 4);                                              \
        cp16(_ad + 32, _as + 8);                                              \
        cp16(_ad + 48, _as + 12);                                             \
        const uint32_t _bd = bB + (uint32_t)_s * B_ST;                        \
        cp16(_bd + brel[0], bsrc[0] + (size_t)(T) * BK);                      \
        cp16(_bd + brel[1], bsrc[1] + (size_t)(T) * BK);                      \
        cp16(_bd + brel[2], bsrc[2] + (size_t)(T) * BK);                      \
        cp16(_bd + brel[3], bsrc[3] + (size_t)(T) * BK);                      \
    } while (0)

#define CONVERT_TILE(T) do {                                                  \
        const uint32_t _sa = bA32 + (uint32_t)((T) & 3) * A32_ST + a32rel;    \
        float4 _f[4];                                                         \
        _Pragma("unroll")                                                     \
        for (int _i = 0; _i < 4; _i++)                                        \
            asm volatile("ld.shared.v4.f32 {%0,%1,%2,%3}, [%4];"              \
                : "=f"(_f[_i].x), "=f"(_f[_i].y), "=f"(_f[_i].z), "=f"(_f[_i].w) \
                : "r"(_sa + 16u * _i));                                       \
        const uint32_t _da = bAbf + (uint32_t)(((T) & 1) ? ABF_ST : 0);       \
        asm volatile("st.shared.v4.b32 [%0], {%1,%2,%3,%4};" ::               \
            "r"(_da + abfrel0),                                               \
            "r"(packbf2(_f[0].x, _f[0].y)), "r"(packbf2(_f[0].z, _f[0].w)),   \
            "r"(packbf2(_f[1].x, _f[1].y)), "r"(packbf2(_f[1].z, _f[1].w)) : "memory"); \
        asm volatile("st.shared.v4.b32 [%0], {%1,%2,%3,%4};" ::               \
            "r"(_da + abfrel1),                                               \
            "r"(packbf2(_f[2].x, _f[2].y)), "r"(packbf2(_f[2].z, _f[2].w)),   \
            "r"(packbf2(_f[3].x, _f[3].y)), "r"(packbf2(_f[3].z, _f[3].w)) : "memory"); \
    } while (0)

    // ---------- prologue: prefill tiles 0..2 ----------
    ISSUE_TILE(0); CP_COMMIT();
    ISSUE_TILE(1); CP_COMMIT();
    ISSUE_TILE(2); CP_COMMIT();
    CP_WAIT2();           // group 0 retired (own A data readable)
    CONVERT_TILE(0);
    __syncthreads();

    // ---------- main loop: one barrier per tile ----------
    for (int kt = 0; kt < NKT; kt++) {
        if (kt + 3 < NKT) ISSUE_TILE(kt + 3);
        CP_COMMIT();

        const uint32_t aoff = bAbf + (uint32_t)((kt & 1) ? ABF_ST : 0);
        const uint32_t boff = bB + (uint32_t)(kt & 3) * B_ST;
#pragma unroll
        for (int ks = 0; ks < 4; ks++) {
            uint32_t a[2][4], b[2][4];
#pragma unroll
            for (int mi = 0; mi < 2; mi++) {
                int c = ks * 2 + achalf;
                ldmx4(a[mi], aoff + (uint32_t)(arow[mi] * 8 + (c ^ (arow[mi] & 7))) * 16);
            }
#pragma unroll
            for (int nj = 0; nj < 2; nj++) {
                int c = ks * 2 + bchalf;
                ldmx4(b[nj], boff + (uint32_t)(brow[nj] * 8 + (c ^ (brow[nj] & 7))) * 16);
            }
#pragma unroll
            for (int mi = 0; mi < 2; mi++)
#pragma unroll
                for (int nt = 0; nt < 4; nt++)
                    mma16816(acc[mi][nt], a[mi], &b[nt >> 1][(nt & 1) * 2]);
        }

        CP_WAIT2();                       // tile kt+1's copies retired (own data)
        if (kt + 1 < NKT) CONVERT_TILE(kt + 1);
        __syncthreads();                  // publish bf16[kt+1], B[kt+1]; free B[kt]
    }

    // ---------- epilogue: -2.5*log10(x) = (-2.5/log2(10)) * log2(x) ----------
    const float C = -0.75257498915995302f;   // -2.5 / log2(10)
#pragma unroll
    for (int mi = 0; mi < 2; mi++) {
        const size_t row0 = bm0 + wmBase + mi * 16 + (lane >> 2);
#pragma unroll
        for (int nt = 0; nt < 4; nt++) {
            const int col = wnBase + nt * 8 + (lane & 3) * 2;
            float2 v0, v1;
            v0.x = C * __log2f(acc[mi][nt][0]);
            v0.y = C * __log2f(acc[mi][nt][1]);
            v1.x = C * __log2f(acc[mi][nt][2]);
            v1.y = C * __log2f(acc[mi][nt][3]);
            *reinterpret_cast<float2*>(out + row0 * BN + col)       = v0;
            *reinterpret_cast<float2*>(out + (row0 + 8) * BN + col) = v1;
        }
    }
}

extern "C" void kernel_launch(void* const* d_in, const int* in_sizes, int n_in,
                              void* d_out, int out_size) {
    const float* l_target = (const float*)d_in[0];   // [B, L] fp32
    const float* trans    = (const float*)d_in[1];   // [F, L] fp32
    const float* lam      = (const float*)d_in[2];   // [L]    fp32

    const int L = in_sizes[2];
    const int F = in_sizes[1] / L;   // 128
    const int B = in_sizes[0] / L;   // 8192
    float* out = (float*)d_out;

    cudaFuncSetAttribute(gemm_log_kernel,
                         cudaFuncAttributeMaxDynamicSharedMemorySize, DYN_SMEM);

    int total4 = (F * L) >> 2;
    wt_kernel<<<(total4 + 255) / 256, 256>>>(trans, lam, F, L);
    gemm_log_kernel<<<B / BM, THREADS, DYN_SMEM>>>(l_target, out, L);
}